// round 2
// baseline (speedup 1.0000x reference)
#include <cuda_runtime.h>

#define NROWS 32768
#define DIM   768
#define NQ    4
#define NV    4096

#define BM 128
#define BN 128
#define BK 16
#define TM 8
#define TN 8
#define NTHREADS 256
#define DELTA 0.05f

// Scratch (allocation-free rule: __device__ globals)
__device__ float  g_residual[(size_t)NROWS * DIM];   // 96 MB
__device__ float  g_quantized[(size_t)NROWS * DIM];  // 96 MB
__device__ float  g_norms[NQ * NV];
__device__ double g_norms64[NQ * NV];
__device__ int    g_indices[NROWS * NQ];
__device__ int    g_nflag[NQ];
__device__ int    g_flaglist[NQ * NROWS];

// ---------------- f32x2 packed helpers ------------------------------------------
__device__ __forceinline__ unsigned long long pack2(float x, float y) {
    unsigned long long r;
    asm("mov.b64 %0, {%1,%2};" : "=l"(r) : "f"(x), "f"(y));
    return r;
}
__device__ __forceinline__ float2 unpack2(unsigned long long v) {
    float2 r;
    asm("mov.b64 {%0,%1}, %2;" : "=f"(r.x), "=f"(r.y) : "l"(v));
    return r;
}
__device__ __forceinline__ void fma2(unsigned long long& d,
                                     unsigned long long a,
                                     unsigned long long b) {
    asm("fma.rn.f32x2 %0, %1, %2, %0;" : "+l"(d) : "l"(a), "l"(b));
}

// ---------------- ||c||^2 per codeword (fp64 + fp32 copy) -----------------------
__global__ void norms_kernel(const float* __restrict__ cb) {
    int w = (blockIdx.x * blockDim.x + threadIdx.x) >> 5;
    int lane = threadIdx.x & 31;
    if (w >= NQ * NV) return;
    const float* c = cb + (size_t)w * DIM;
    double s = 0.0;
    #pragma unroll 4
    for (int d = lane; d < DIM; d += 32) {
        double v = (double)__ldg(c + d);
        s = fma(v, v, s);
    }
    #pragma unroll
    for (int o = 16; o; o >>= 1) s += __shfl_xor_sync(0xffffffffu, s, o);
    if (lane == 0) { g_norms64[w] = s; g_norms[w] = (float)s; }
}

// ---------------- residual = x, quantized = 0, flag counters = 0 ----------------
__global__ void init_kernel(const float* __restrict__ x) {
    size_t i = (size_t)blockIdx.x * blockDim.x + threadIdx.x;
    if (i < NQ) g_nflag[i] = 0;
    if (i >= (size_t)NROWS * DIM / 4) return;
    float4 v = ((const float4*)x)[i];
    ((float4*)g_residual)[i] = v;
    ((float4*)g_quantized)[i] = make_float4(0.f, 0.f, 0.f, 0.f);
}

// ---------------- fused GEMM + running top-2 argmax: one level ------------------
__global__ void __launch_bounds__(NTHREADS, 1)
score_kernel(const float* __restrict__ cb, int q) {
    __shared__ float As[2][BK][BM];
    __shared__ float Bs[2][BK][BN];

    const int tid = threadIdx.x;
    const int tx = tid & 15;         // N direction (16)
    const int ty = tid >> 4;         // M direction (16)
    const int block_m = blockIdx.x * BM;
    const int lrow = tid >> 2;       // 0..63 : row-within-tile for loads
    const int lk   = (tid & 3) << 2; // 0,4,8,12 : k offset (float4)

    const float* Abase = g_residual + (size_t)block_m * DIM;
    const float* nbase = g_norms + q * NV;

    float s1[TM], s2[TM];
    int   v1[TM];
    #pragma unroll
    for (int i = 0; i < TM; i++) { s1[i] = -1e30f; s2[i] = -1e30f; v1[i] = 0; }

    const int KT = DIM / BK;  // 48

    for (int vt = 0; vt < NV / BN; ++vt) {
        const float* Bbase = cb + (size_t)vt * BN * DIM;

        unsigned long long acc[TM][TN / 2];
        #pragma unroll
        for (int i = 0; i < TM; i++)
            #pragma unroll
            for (int j = 0; j < TN / 2; j++) acc[i][j] = 0ULL;

        float4 areg[2], breg[2];
        #pragma unroll
        for (int i = 0; i < 2; i++) {
            areg[i] = *(const float4*)(Abase + (size_t)(lrow + 64 * i) * DIM + lk);
            breg[i] = *(const float4*)(Bbase + (size_t)(lrow + 64 * i) * DIM + lk);
        }
        #pragma unroll
        for (int i = 0; i < 2; i++) {
            int r = lrow + 64 * i;
            As[0][lk + 0][r] = areg[i].x; As[0][lk + 1][r] = areg[i].y;
            As[0][lk + 2][r] = areg[i].z; As[0][lk + 3][r] = areg[i].w;
            Bs[0][lk + 0][r] = breg[i].x; Bs[0][lk + 1][r] = breg[i].y;
            Bs[0][lk + 2][r] = breg[i].z; Bs[0][lk + 3][r] = breg[i].w;
        }
        __syncthreads();

        int buf = 0;
        for (int kt = 0; kt < KT; ++kt) {
            if (kt + 1 < KT) {
                int k0 = (kt + 1) * BK + lk;
                #pragma unroll
                for (int i = 0; i < 2; i++) {
                    areg[i] = *(const float4*)(Abase + (size_t)(lrow + 64 * i) * DIM + k0);
                    breg[i] = *(const float4*)(Bbase + (size_t)(lrow + 64 * i) * DIM + k0);
                }
            }
            #pragma unroll
            for (int kk = 0; kk < BK; kk++) {
                const float* arow = &As[buf][kk][ty * TM];
                float4 av0 = *(const float4*)(arow);
                float4 av1 = *(const float4*)(arow + 4);
                unsigned long long a2[TM];
                a2[0] = pack2(av0.x, av0.x); a2[1] = pack2(av0.y, av0.y);
                a2[2] = pack2(av0.z, av0.z); a2[3] = pack2(av0.w, av0.w);
                a2[4] = pack2(av1.x, av1.x); a2[5] = pack2(av1.y, av1.y);
                a2[6] = pack2(av1.z, av1.z); a2[7] = pack2(av1.w, av1.w);

                const ulonglong2* bp = (const ulonglong2*)&Bs[buf][kk][tx * TN];
                ulonglong2 bv0 = bp[0], bv1 = bp[1];
                unsigned long long b2[4] = {bv0.x, bv0.y, bv1.x, bv1.y};

                #pragma unroll
                for (int i = 0; i < TM; i++) {
                    #pragma unroll
                    for (int j = 0; j < 4; j++) fma2(acc[i][j], a2[i], b2[j]);
                }
            }
            if (kt + 1 < KT) {
                int nb = buf ^ 1;
                #pragma unroll
                for (int i = 0; i < 2; i++) {
                    int r = lrow + 64 * i;
                    As[nb][lk + 0][r] = areg[i].x; As[nb][lk + 1][r] = areg[i].y;
                    As[nb][lk + 2][r] = areg[i].z; As[nb][lk + 3][r] = areg[i].w;
                    Bs[nb][lk + 0][r] = breg[i].x; Bs[nb][lk + 1][r] = breg[i].y;
                    Bs[nb][lk + 2][r] = breg[i].z; Bs[nb][lk + 3][r] = breg[i].w;
                }
                __syncthreads();
                buf = nb;
            }
        }

        // epilogue: score = 2*dot - ||c||^2 ; running TOP-2 (ascending v ->
        // strict > keeps the first max, matching jnp.argmax)
        const float* nrm = nbase + vt * BN + tx * TN;
        int vb = vt * BN + tx * TN;
        #pragma unroll
        for (int j = 0; j < TN / 2; j++) {
            float n0 = __ldg(nrm + 2 * j);
            float n1 = __ldg(nrm + 2 * j + 1);
            #pragma unroll
            for (int i = 0; i < TM; i++) {
                float2 s = unpack2(acc[i][j]);
                float sc0 = fmaf(2.f, s.x, -n0);
                float sc1 = fmaf(2.f, s.y, -n1);
                if (sc0 > s1[i]) { s2[i] = s1[i]; s1[i] = sc0; v1[i] = vb + 2 * j; }
                else if (sc0 > s2[i]) s2[i] = sc0;
                if (sc1 > s1[i]) { s2[i] = s1[i]; s1[i] = sc1; v1[i] = vb + 2 * j + 1; }
                else if (sc1 > s2[i]) s2[i] = sc1;
            }
        }
    }

    // cross-lane top-2 merge over the 16 tx lanes (candidate sets are disjoint)
    #pragma unroll
    for (int i = 0; i < TM; i++) {
        float b1 = s1[i], b2 = s2[i];
        int bi = v1[i];
        #pragma unroll
        for (int o = 1; o < 16; o <<= 1) {
            float t1 = __shfl_xor_sync(0xffffffffu, b1, o);
            int   w1 = __shfl_xor_sync(0xffffffffu, bi, o);
            float t2 = __shfl_xor_sync(0xffffffffu, b2, o);
            if (t1 > b1 || (t1 == b1 && w1 < bi)) {
                b2 = fmaxf(b1, t2); b1 = t1; bi = w1;
            } else {
                b2 = fmaxf(b2, t1);
            }
        }
        if (tx == 0) {
            int row = block_m + ty * TM + i;
            g_indices[row * NQ + q] = bi;
            if (b1 - b2 < DELTA) {
                int p = atomicAdd(&g_nflag[q], 1);
                g_flaglist[q * NROWS + p] = row;
            }
        }
    }
}

// ---------------- fp64 exhaustive refine for near-tie rows ----------------------
__global__ void __launch_bounds__(256, 1)
refine_kernel(const float* __restrict__ cb, int q) {
    __shared__ float  rsm[DIM];
    __shared__ double sred[256];
    __shared__ int    ired[256];

    const int tid = threadIdx.x;
    const int nf = g_nflag[q];

    for (int jj = blockIdx.x; jj < nf; jj += gridDim.x) {
        const int row = g_flaglist[q * NROWS + jj];
        for (int d = tid; d < DIM; d += 256) rsm[d] = g_residual[(size_t)row * DIM + d];
        __syncthreads();

        double best = -1e300;
        int bidx = 0;
        for (int v = tid; v < NV; v += 256) {
            const float4* cv = (const float4*)(cb + (size_t)v * DIM);
            double a0 = 0, a1 = 0, a2 = 0, a3 = 0, a4 = 0, a5 = 0, a6 = 0, a7 = 0;
            #pragma unroll 4
            for (int t = 0; t < DIM / 4; t += 2) {
                float4 c0 = __ldg(cv + t);
                float4 c1 = __ldg(cv + t + 1);
                const float4 r0 = *(const float4*)&rsm[4 * t];
                const float4 r1 = *(const float4*)&rsm[4 * t + 4];
                a0 = fma((double)r0.x, (double)c0.x, a0);
                a1 = fma((double)r0.y, (double)c0.y, a1);
                a2 = fma((double)r0.z, (double)c0.z, a2);
                a3 = fma((double)r0.w, (double)c0.w, a3);
                a4 = fma((double)r1.x, (double)c1.x, a4);
                a5 = fma((double)r1.y, (double)c1.y, a5);
                a6 = fma((double)r1.z, (double)c1.z, a6);
                a7 = fma((double)r1.w, (double)c1.w, a7);
            }
            double dot = ((a0 + a1) + (a2 + a3)) + ((a4 + a5) + (a6 + a7));
            double s = 2.0 * dot - g_norms64[q * NV + v];
            if (s > best) { best = s; bidx = v; }  // ascending v: first max wins
        }
        sred[tid] = best; ired[tid] = bidx;
        __syncthreads();
        for (int o = 128; o; o >>= 1) {
            if (tid < o) {
                double so = sred[tid + o]; int vo = ired[tid + o];
                if (so > sred[tid] || (so == sred[tid] && vo < ired[tid])) {
                    sred[tid] = so; ired[tid] = vo;
                }
            }
            __syncthreads();
        }
        if (tid == 0) g_indices[row * NQ + q] = ired[0];
        __syncthreads();
    }
}

// ---------------- gather + residual/quantized update ----------------------------
__global__ void update_kernel(const float* __restrict__ cb, int q) {
    int gid = blockIdx.x * blockDim.x + threadIdx.x;
    const int PR = DIM / 4;  // 192 float4 per row
    int row = gid / PR;
    if (row >= NROWS) return;
    int c = (gid - row * PR) << 2;
    int idx = __ldg(&g_indices[row * NQ + q]);
    const float4 cw = *(const float4*)(cb + (size_t)idx * DIM + c);
    size_t off = (size_t)row * DIM + c;
    float4 r = *(float4*)(g_residual + off);
    float4 z = *(float4*)(g_quantized + off);
    r.x -= cw.x; r.y -= cw.y; r.z -= cw.z; r.w -= cw.w;
    z.x += cw.x; z.y += cw.y; z.z += cw.z; z.w += cw.w;
    *(float4*)(g_residual + off) = r;
    *(float4*)(g_quantized + off) = z;
}

// ---------------- out = x + (quantized - x) (STE forward) -----------------------
__global__ void finalize_kernel(const float* __restrict__ x, float* __restrict__ out) {
    size_t i = (size_t)blockIdx.x * blockDim.x + threadIdx.x;
    if (i >= (size_t)NROWS * DIM / 4) return;
    float4 xv = ((const float4*)x)[i];
    float4 qv = ((const float4*)g_quantized)[i];
    float4 o;
    o.x = xv.x + (qv.x - xv.x);
    o.y = xv.y + (qv.y - xv.y);
    o.z = xv.z + (qv.z - xv.z);
    o.w = xv.w + (qv.w - xv.w);
    ((float4*)out)[i] = o;
}

// indices as float in the tail of d_out (if the harness expects both outputs)
__global__ void idxout_kernel(float* __restrict__ out) {
    int i = blockIdx.x * blockDim.x + threadIdx.x;
    if (i < NROWS * NQ) out[i] = (float)g_indices[i];
}

extern "C" void kernel_launch(void* const* d_in, const int* in_sizes, int n_in,
                              void* d_out, int out_size) {
    const float* x  = (const float*)d_in[0];
    const float* cb = (const float*)d_in[1];
    float* out = (float*)d_out;

    norms_kernel<<<(NQ * NV) / 8, 256>>>(cb);
    init_kernel<<<(NROWS * DIM / 4 + 255) / 256, 256>>>(x);

    for (int q = 0; q < NQ; q++) {
        const float* cbq = cb + (size_t)q * NV * DIM;
        score_kernel<<<NROWS / BM, NTHREADS>>>(cbq, q);
        refine_kernel<<<448, 256>>>(cbq, q);
        update_kernel<<<(NROWS * (DIM / 4) + 255) / 256, 256>>>(cbq, q);
    }

    finalize_kernel<<<(NROWS * DIM / 4 + 255) / 256, 256>>>(x, out);

    if (out_size >= NROWS * DIM + NROWS * NQ) {
        idxout_kernel<<<(NROWS * NQ + 255) / 256, 256>>>(out + (size_t)NROWS * DIM);
    }
}

// round 5
// speedup vs baseline: 1.6573x; 1.6573x over previous
#include <cuda_runtime.h>
#include <cuda_bf16.h>
#include <cstdint>

#define NROWS 32768
#define DIM   768
#define NQ    4
#define NV    4096
#define DELTA 0.02f

#define GBM 128
#define GBN 128
#define KTOT 2304          // 3*768 effective K
#define BK   32
#define NSTG (KTOT / BK)   // 72
#define NT2  (NV / GBN)    // 32 n-tiles
#define MT2  (NROWS / GBM) // 256 m-tiles
#define ACOLS 1536         // [r0 | r1]
#define BCOLS 2304         // [c0 | c1 | c0]
#define SSTRIDE 40         // bf16 elems per smem row (32 + 8 pad) -> 80 bytes
#define NSEG 128           // NT2 * 4 warp-col segments of 32 cols

// ---------------- scratch ---------------------------------------------------------
__device__ float  g_residual[(size_t)NROWS * DIM];
__device__ float  g_quantized[(size_t)NROWS * DIM];
__device__ float  g_norms[NQ * NV];
__device__ double g_norms64[NQ * NV];
__device__ int    g_indices[NROWS * NQ];
__device__ int    g_nflag[NQ];
__device__ int    g_flaglist[NQ * NROWS];
__device__ __align__(256) __nv_bfloat16 g_Asplit[(size_t)NROWS * ACOLS];     // 100 MB
__device__ __align__(256) __nv_bfloat16 g_Bsplit[(size_t)NQ * NV * BCOLS];  // 75 MB
__device__ float4 g_part[(size_t)NROWS * NSEG];                             // 64 MB

// ---------------- PTX helpers ------------------------------------------------------
__device__ __forceinline__ uint32_t smem_u32(const void* p) {
    uint32_t a;
    asm("{ .reg .u64 t; cvta.to.shared.u64 t, %1; cvt.u32.u64 %0, t; }" : "=r"(a) : "l"(p));
    return a;
}
__device__ __forceinline__ void cp16(uint32_t s, const void* g) {
    asm volatile("cp.async.cg.shared.global [%0], [%1], 16;" :: "r"(s), "l"(g));
}
__device__ __forceinline__ void cp_commit() { asm volatile("cp.async.commit_group;"); }
template <int N>
__device__ __forceinline__ void cp_wait() { asm volatile("cp.async.wait_group %0;" :: "n"(N) : "memory"); }

__device__ __forceinline__ void ldm_x4(uint32_t* r, uint32_t a) {
    asm volatile("ldmatrix.sync.aligned.m8n8.x4.shared.b16 {%0,%1,%2,%3}, [%4];"
                 : "=r"(r[0]), "=r"(r[1]), "=r"(r[2]), "=r"(r[3]) : "r"(a));
}
__device__ __forceinline__ void ldm_x2(uint32_t* r, uint32_t a) {
    asm volatile("ldmatrix.sync.aligned.m8n8.x2.shared.b16 {%0,%1}, [%2];"
                 : "=r"(r[0]), "=r"(r[1]) : "r"(a));
}
__device__ __forceinline__ void mma16816(float* d, const uint32_t* a, const uint32_t* b) {
    asm volatile("mma.sync.aligned.m16n8k16.row.col.f32.bf16.bf16.f32 "
                 "{%0,%1,%2,%3}, {%4,%5,%6,%7}, {%8,%9}, {%0,%1,%2,%3};"
                 : "+f"(d[0]), "+f"(d[1]), "+f"(d[2]), "+f"(d[3])
                 : "r"(a[0]), "r"(a[1]), "r"(a[2]), "r"(a[3]), "r"(b[0]), "r"(b[1]));
}

// ---------------- ||c||^2 per codeword (fp64 + fp32 copy) --------------------------
__global__ void norms_kernel(const float* __restrict__ cb) {
    int w = (blockIdx.x * blockDim.x + threadIdx.x) >> 5;
    int lane = threadIdx.x & 31;
    if (w >= NQ * NV) return;
    const float* c = cb + (size_t)w * DIM;
    double s = 0.0;
    #pragma unroll 4
    for (int d = lane; d < DIM; d += 32) {
        double v = (double)__ldg(c + d);
        s = fma(v, v, s);
    }
    #pragma unroll
    for (int o = 16; o; o >>= 1) s += __shfl_xor_sync(0xffffffffu, s, o);
    if (lane == 0) { g_norms64[w] = s; g_norms[w] = (float)s; }
}

// ---------------- residual = x, quantized = 0, flags = 0 ---------------------------
__global__ void init_kernel(const float* __restrict__ x) {
    size_t i = (size_t)blockIdx.x * blockDim.x + threadIdx.x;
    if (i < NQ) g_nflag[i] = 0;
    if (i >= (size_t)NROWS * DIM / 4) return;
    float4 v = ((const float4*)x)[i];
    ((float4*)g_residual)[i] = v;
    ((float4*)g_quantized)[i] = make_float4(0.f, 0.f, 0.f, 0.f);
}

// ---------------- split codebooks (once): B' = [c0 | c1 | c0] bf16 ------------------
__global__ void splitB_kernel(const float* __restrict__ cb) {
    int i = blockIdx.x * blockDim.x + threadIdx.x;
    if (i >= NQ * NV * (DIM / 4)) return;
    int qv = i / (DIM / 4);
    int d4 = (i - qv * (DIM / 4)) * 4;
    float4 v = *(const float4*)(cb + (size_t)qv * DIM + d4);
    __nv_bfloat16 h0 = __float2bfloat16_rn(v.x), h1 = __float2bfloat16_rn(v.y);
    __nv_bfloat16 h2 = __float2bfloat16_rn(v.z), h3 = __float2bfloat16_rn(v.w);
    __nv_bfloat16 l0 = __float2bfloat16_rn(v.x - __bfloat162float(h0));
    __nv_bfloat16 l1 = __float2bfloat16_rn(v.y - __bfloat162float(h1));
    __nv_bfloat16 l2 = __float2bfloat16_rn(v.z - __bfloat162float(h2));
    __nv_bfloat16 l3 = __float2bfloat16_rn(v.w - __bfloat162float(h3));
    __nv_bfloat16* base = g_Bsplit + (size_t)qv * BCOLS;
    __nv_bfloat162 hA = {h0, h1}, hB = {h2, h3}, lA = {l0, l1}, lB = {l2, l3};
    *(__nv_bfloat162*)(base + d4)            = hA;
    *(__nv_bfloat162*)(base + d4 + 2)        = hB;
    *(__nv_bfloat162*)(base + 768 + d4)      = lA;
    *(__nv_bfloat162*)(base + 768 + d4 + 2)  = lB;
    *(__nv_bfloat162*)(base + 1536 + d4)     = hA;
    *(__nv_bfloat162*)(base + 1536 + d4 + 2) = hB;
}

// ---------------- split residual (per level): A' = [r0 | r1] bf16 -------------------
__global__ void splitA_kernel() {
    int i = blockIdx.x * blockDim.x + threadIdx.x;
    if (i >= NROWS * (DIM / 4)) return;
    int row = i / (DIM / 4);
    int d4 = (i - row * (DIM / 4)) * 4;
    float4 v = *(const float4*)(g_residual + (size_t)row * DIM + d4);
    __nv_bfloat16 h0 = __float2bfloat16_rn(v.x), h1 = __float2bfloat16_rn(v.y);
    __nv_bfloat16 h2 = __float2bfloat16_rn(v.z), h3 = __float2bfloat16_rn(v.w);
    __nv_bfloat16 l0 = __float2bfloat16_rn(v.x - __bfloat162float(h0));
    __nv_bfloat16 l1 = __float2bfloat16_rn(v.y - __bfloat162float(h1));
    __nv_bfloat16 l2 = __float2bfloat16_rn(v.z - __bfloat162float(h2));
    __nv_bfloat16 l3 = __float2bfloat16_rn(v.w - __bfloat162float(h3));
    __nv_bfloat16* base = g_Asplit + (size_t)row * ACOLS;
    *(__nv_bfloat162*)(base + d4)           = __nv_bfloat162{h0, h1};
    *(__nv_bfloat162*)(base + d4 + 2)       = __nv_bfloat162{h2, h3};
    *(__nv_bfloat162*)(base + 768 + d4)     = __nv_bfloat162{l0, l1};
    *(__nv_bfloat162*)(base + 768 + d4 + 2) = __nv_bfloat162{l2, l3};
}

// ---------------- mma.sync score GEMM + per-row/segment top-2 ----------------------
// grid = MT2*NT2 (nt fastest), 256 threads = 8 warps (2 m x 4 n), warp tile 64x32
// NOTE: B pointer computed IN-KERNEL from q (device symbol not valid from host).
__global__ void __launch_bounds__(256)
score_gemm_kernel(int q) {
    __shared__ __align__(16) __nv_bfloat16 sA[2][GBM * SSTRIDE];
    __shared__ __align__(16) __nv_bfloat16 sB[2][GBN * SSTRIDE];
    __shared__ float snorm[GBN];

    const __nv_bfloat16* __restrict__ Bq = g_Bsplit + (size_t)q * NV * BCOLS;

    const int tid = threadIdx.x;
    const int wid = tid >> 5;
    const int lane = tid & 31;
    const int nt = blockIdx.x & (NT2 - 1);
    const int mt = blockIdx.x >> 5;
    const int block_m = mt * GBM;
    const int ncol0 = nt * GBN;
    const int warp_m = (wid >> 2) * 64;   // 0 or 64
    const int warp_n = (wid & 3) * 32;    // 0,32,64,96

    if (tid < GBN) snorm[tid] = g_norms[q * NV + ncol0 + tid];

    const uint32_t sA0 = smem_u32(&sA[0][0]), sA1 = smem_u32(&sA[1][0]);
    const uint32_t sB0 = smem_u32(&sB[0][0]), sB1 = smem_u32(&sB[1][0]);

    auto issue = [&](int s, int b) {
        const int k0 = s * BK;
        const int acol = k0 - (k0 >= 768 ? 768 : 0);
        const char* Ab = (const char*)g_Asplit + ((size_t)block_m * ACOLS + acol) * 2;
        const char* Bb = (const char*)Bq + ((size_t)ncol0 * BCOLS + k0) * 2;
        const uint32_t dA = b ? sA1 : sA0;
        const uint32_t dB = b ? sB1 : sB0;
        #pragma unroll
        for (int i = 0; i < 2; i++) {            // 512 A chunks of 16B
            int ch = tid + i * 256;
            int r = ch >> 2, c16 = (ch & 3) * 16;
            cp16(dA + r * (SSTRIDE * 2) + c16, Ab + (size_t)r * (ACOLS * 2) + c16);
        }
        #pragma unroll
        for (int i = 0; i < 2; i++) {            // 512 B chunks
            int ch = tid + i * 256;
            int r = ch >> 2, c16 = (ch & 3) * 16;
            cp16(dB + r * (SSTRIDE * 2) + c16, Bb + (size_t)r * (BCOLS * 2) + c16);
        }
        cp_commit();
    };

    float acc[4][4][4];
    #pragma unroll
    for (int im = 0; im < 4; im++)
        #pragma unroll
        for (int in = 0; in < 4; in++)
            #pragma unroll
            for (int e = 0; e < 4; e++) acc[im][in][e] = 0.f;

    issue(0, 0);
    issue(1, 1);

    const int arow = lane & 15;
    const int acolh = (lane >> 4) * 8;
    const int brow = lane & 7;
    const int bcolh = ((lane >> 3) & 1) * 8;

    #pragma unroll 1
    for (int s = 0; s < NSTG; ++s) {
        if (s < NSTG - 1) cp_wait<1>(); else cp_wait<0>();
        __syncthreads();
        const int bf = s & 1;
        const uint32_t aB = bf ? sA1 : sA0;
        const uint32_t bB = bf ? sB1 : sB0;
        #pragma unroll
        for (int kk = 0; kk < 2; kk++) {
            const int k0 = kk * 16;
            uint32_t afr[4][4];
            #pragma unroll
            for (int im = 0; im < 4; im++) {
                uint32_t addr = aB + ((warp_m + im * 16 + arow) * SSTRIDE + k0 + acolh) * 2;
                ldm_x4(afr[im], addr);
            }
            #pragma unroll
            for (int in = 0; in < 4; in++) {
                uint32_t bfr[2];
                uint32_t addr = bB + ((warp_n + in * 8 + brow) * SSTRIDE + k0 + bcolh) * 2;
                ldm_x2(bfr, addr);
                #pragma unroll
                for (int im = 0; im < 4; im++) mma16816(acc[im][in], afr[im], bfr);
            }
        }
        __syncthreads();
        if (s + 2 < NSTG) issue(s + 2, bf);
    }

    // epilogue: per-row top-2 over this warp's 32 cols; quad-merge; write partials.
    const int seg = nt * 4 + (wid & 3);
    #pragma unroll
    for (int im = 0; im < 4; im++) {
        float t1a = -1e30f, t2a = -1e30f, t1b = -1e30f, t2b = -1e30f;
        int i1a = 0, i1b = 0;
        #pragma unroll
        for (int in = 0; in < 4; in++) {
            int c = warp_n + in * 8 + (lane & 3) * 2;
            float n0 = snorm[c], n1 = snorm[c + 1];
            float sa0 = fmaf(2.f, acc[im][in][0], -n0);
            float sa1 = fmaf(2.f, acc[im][in][1], -n1);
            float sb0 = fmaf(2.f, acc[im][in][2], -n0);
            float sb1 = fmaf(2.f, acc[im][in][3], -n1);
            int gc = ncol0 + c;
            if (sa0 > t1a) { t2a = t1a; t1a = sa0; i1a = gc; } else if (sa0 > t2a) t2a = sa0;
            if (sa1 > t1a) { t2a = t1a; t1a = sa1; i1a = gc + 1; } else if (sa1 > t2a) t2a = sa1;
            if (sb0 > t1b) { t2b = t1b; t1b = sb0; i1b = gc; } else if (sb0 > t2b) t2b = sb0;
            if (sb1 > t1b) { t2b = t1b; t1b = sb1; i1b = gc + 1; } else if (sb1 > t2b) t2b = sb1;
        }
        #pragma unroll
        for (int o = 1; o < 4; o <<= 1) {
            float u1 = __shfl_xor_sync(0xffffffffu, t1a, o);
            float u2 = __shfl_xor_sync(0xffffffffu, t2a, o);
            int   ui = __shfl_xor_sync(0xffffffffu, i1a, o);
            if (u1 > t1a || (u1 == t1a && ui < i1a)) { t2a = fmaxf(t1a, u2); t1a = u1; i1a = ui; }
            else t2a = fmaxf(t2a, u1);
            float v1 = __shfl_xor_sync(0xffffffffu, t1b, o);
            float v2 = __shfl_xor_sync(0xffffffffu, t2b, o);
            int   vi = __shfl_xor_sync(0xffffffffu, i1b, o);
            if (v1 > t1b || (v1 == t1b && vi < i1b)) { t2b = fmaxf(t1b, v2); t1b = v1; i1b = vi; }
            else t2b = fmaxf(t2b, v1);
        }
        if ((lane & 3) == 0) {
            int rA = block_m + warp_m + im * 16 + (lane >> 2);
            g_part[(size_t)rA * NSEG + seg] = make_float4(t1a, t2a, __int_as_float(i1a), 0.f);
            g_part[(size_t)(rA + 8) * NSEG + seg] = make_float4(t1b, t2b, __int_as_float(i1b), 0.f);
        }
    }
}

// ---------------- merge partials -> global top-2, index, flag list ------------------
__global__ void merge_kernel(int q) {
    int row = blockIdx.x * blockDim.x + threadIdx.x;
    if (row >= NROWS) return;
    float b1 = -1e30f, b2 = -1e30f;
    int bi = 0;
    const float4* p = &g_part[(size_t)row * NSEG];
    #pragma unroll 8
    for (int s = 0; s < NSEG; s++) {
        float4 v = p[s];   // segments ascending in col index: first-max-wins
        if (v.x > b1) { b2 = fmaxf(b1, v.y); b1 = v.x; bi = __float_as_int(v.z); }
        else          { b2 = fmaxf(b2, v.x); }
    }
    g_indices[row * NQ + q] = bi;
    if (b1 - b2 < DELTA) {
        int pos = atomicAdd(&g_nflag[q], 1);
        g_flaglist[q * NROWS + pos] = row;
    }
}

// ---------------- fp64 exhaustive refine for near-tie rows --------------------------
__global__ void __launch_bounds__(256, 1)
refine_kernel(const float* __restrict__ cb, int q) {
    __shared__ float  rsm[DIM];
    __shared__ double sred[256];
    __shared__ int    ired[256];

    const int tid = threadIdx.x;
    const int nf = g_nflag[q];

    for (int jj = blockIdx.x; jj < nf; jj += gridDim.x) {
        const int row = g_flaglist[q * NROWS + jj];
        for (int d = tid; d < DIM; d += 256) rsm[d] = g_residual[(size_t)row * DIM + d];
        __syncthreads();

        double best = -1e300;
        int bidx = 0;
        for (int v = tid; v < NV; v += 256) {
            const float4* cv = (const float4*)(cb + (size_t)v * DIM);
            double a0 = 0, a1 = 0, a2 = 0, a3 = 0, a4 = 0, a5 = 0, a6 = 0, a7 = 0;
            #pragma unroll 4
            for (int t = 0; t < DIM / 4; t += 2) {
                float4 c0 = __ldg(cv + t);
                float4 c1 = __ldg(cv + t + 1);
                const float4 r0 = *(const float4*)&rsm[4 * t];
                const float4 r1 = *(const float4*)&rsm[4 * t + 4];
                a0 = fma((double)r0.x, (double)c0.x, a0);
                a1 = fma((double)r0.y, (double)c0.y, a1);
                a2 = fma((double)r0.z, (double)c0.z, a2);
                a3 = fma((double)r0.w, (double)c0.w, a3);
                a4 = fma((double)r1.x, (double)c1.x, a4);
                a5 = fma((double)r1.y, (double)c1.y, a5);
                a6 = fma((double)r1.z, (double)c1.z, a6);
                a7 = fma((double)r1.w, (double)c1.w, a7);
            }
            double dot = ((a0 + a1) + (a2 + a3)) + ((a4 + a5) + (a6 + a7));
            double s = 2.0 * dot - g_norms64[q * NV + v];
            if (s > best) { best = s; bidx = v; }
        }
        sred[tid] = best; ired[tid] = bidx;
        __syncthreads();
        for (int o = 128; o; o >>= 1) {
            if (tid < o) {
                double so = sred[tid + o]; int vo = ired[tid + o];
                if (so > sred[tid] || (so == sred[tid] && vo < ired[tid])) {
                    sred[tid] = so; ired[tid] = vo;
                }
            }
            __syncthreads();
        }
        if (tid == 0) g_indices[row * NQ + q] = ired[0];
        __syncthreads();
    }
}

// ---------------- gather + residual/quantized update --------------------------------
__global__ void update_kernel(const float* __restrict__ cb, int q) {
    int gid = blockIdx.x * blockDim.x + threadIdx.x;
    const int PR = DIM / 4;
    int row = gid / PR;
    if (row >= NROWS) return;
    int c = (gid - row * PR) << 2;
    int idx = __ldg(&g_indices[row * NQ + q]);
    const float4 cw = *(const float4*)(cb + (size_t)idx * DIM + c);
    size_t off = (size_t)row * DIM + c;
    float4 r = *(float4*)(g_residual + off);
    float4 z = *(float4*)(g_quantized + off);
    r.x -= cw.x; r.y -= cw.y; r.z -= cw.z; r.w -= cw.w;
    z.x += cw.x; z.y += cw.y; z.z += cw.z; z.w += cw.w;
    *(float4*)(g_residual + off) = r;
    *(float4*)(g_quantized + off) = z;
}

// ---------------- out = x + (quantized - x) -----------------------------------------
__global__ void finalize_kernel(const float* __restrict__ x, float* __restrict__ out) {
    size_t i = (size_t)blockIdx.x * blockDim.x + threadIdx.x;
    if (i >= (size_t)NROWS * DIM / 4) return;
    float4 xv = ((const float4*)x)[i];
    float4 qv = ((const float4*)g_quantized)[i];
    float4 o;
    o.x = xv.x + (qv.x - xv.x);
    o.y = xv.y + (qv.y - xv.y);
    o.z = xv.z + (qv.z - xv.z);
    o.w = xv.w + (qv.w - xv.w);
    ((float4*)out)[i] = o;
}

__global__ void idxout_kernel(float* __restrict__ out) {
    int i = blockIdx.x * blockDim.x + threadIdx.x;
    if (i < NROWS * NQ) out[i] = (float)g_indices[i];
}

extern "C" void kernel_launch(void* const* d_in, const int* in_sizes, int n_in,
                              void* d_out, int out_size) {
    const float* x  = (const float*)d_in[0];
    const float* cb = (const float*)d_in[1];
    float* out = (float*)d_out;

    norms_kernel<<<(NQ * NV) / 8, 256>>>(cb);
    init_kernel<<<(NROWS * DIM / 4 + 255) / 256, 256>>>(x);
    splitB_kernel<<<(NQ * NV * (DIM / 4) + 255) / 256, 256>>>(cb);

    for (int q = 0; q < NQ; q++) {
        const float* cbq = cb + (size_t)q * NV * DIM;
        splitA_kernel<<<(NROWS * (DIM / 4) + 255) / 256, 256>>>();
        score_gemm_kernel<<<MT2 * NT2, 256>>>(q);
        merge_kernel<<<(NROWS + 255) / 256, 256>>>(q);
        refine_kernel<<<148, 256>>>(cbq, q);
        update_kernel<<<(NROWS * (DIM / 4) + 255) / 256, 256>>>(cbq, q);
    }

    finalize_kernel<<<(NROWS * DIM / 4 + 255) / 256, 256>>>(x, out);

    if (out_size >= NROWS * DIM + NROWS * NQ) {
        idxout_kernel<<<(NROWS * NQ + 255) / 256, 256>>>(out + (size_t)NROWS * DIM);
    }
}

// round 6
// speedup vs baseline: 1.8663x; 1.1261x over previous
#include <cuda_runtime.h>
#include <cuda_fp16.h>
#include <cstdint>

#define NROWS 32768
#define DIM   768
#define NQ    4
#define NV    4096
#define DELTA 1e-3f

#define GBM 128
#define GBN 128
#define KTOT 2304          // 3*768 effective K: r0c0 + r0c1 + r1c0
#define BK   64
#define NSTG (KTOT / BK)   // 36
#define NBUF 3
#define NT2  (NV / GBN)    // 32
#define MT2  (NROWS / GBM) // 256
#define ACOLS 1536         // [r0 | r1]
#define BCOLS 2304         // [c0 | c1 | c0]
#define SROW  72           // half elems per smem row (64 + 8 pad)
#define SROWB 144          // bytes per smem row
#define BUFSZ (128 * SROWB)            // 18432 B per matrix per buffer
#define SMEM_DYN (NBUF * 2 * BUFSZ)    // 110592 B
#define NSEG 128           // NT2 * 4 warp-col segments of 32 cols

// ---------------- scratch ---------------------------------------------------------
__device__ float  g_residual[(size_t)NROWS * DIM];
__device__ float  g_quantized[(size_t)NROWS * DIM];
__device__ float  g_norms[NQ * NV];
__device__ double g_norms64[NQ * NV];
__device__ int    g_indices[NROWS * NQ];
__device__ int    g_nflag[NQ];
__device__ int    g_flaglist[NQ * NROWS];
__device__ __align__(256) __half g_Asplit[(size_t)NROWS * ACOLS];     // 100 MB
__device__ __align__(256) __half g_Bsplit[(size_t)NQ * NV * BCOLS];   // 75 MB
__device__ float4 g_part[(size_t)NROWS * NSEG];                       // 64 MB

// ---------------- PTX helpers ------------------------------------------------------
__device__ __forceinline__ uint32_t smem_u32(const void* p) {
    uint32_t a;
    asm("{ .reg .u64 t; cvta.to.shared.u64 t, %1; cvt.u32.u64 %0, t; }" : "=r"(a) : "l"(p));
    return a;
}
__device__ __forceinline__ void cp16(uint32_t s, const void* g) {
    asm volatile("cp.async.cg.shared.global [%0], [%1], 16;" :: "r"(s), "l"(g));
}
__device__ __forceinline__ void cp_commit() { asm volatile("cp.async.commit_group;"); }
template <int N>
__device__ __forceinline__ void cp_wait() { asm volatile("cp.async.wait_group %0;" :: "n"(N) : "memory"); }

__device__ __forceinline__ void ldm_x4(uint32_t* r, uint32_t a) {
    asm volatile("ldmatrix.sync.aligned.m8n8.x4.shared.b16 {%0,%1,%2,%3}, [%4];"
                 : "=r"(r[0]), "=r"(r[1]), "=r"(r[2]), "=r"(r[3]) : "r"(a));
}
__device__ __forceinline__ void ldm_x2(uint32_t* r, uint32_t a) {
    asm volatile("ldmatrix.sync.aligned.m8n8.x2.shared.b16 {%0,%1}, [%2];"
                 : "=r"(r[0]), "=r"(r[1]) : "r"(a));
}
__device__ __forceinline__ void mma16816(float* d, const uint32_t* a, const uint32_t* b) {
    asm volatile("mma.sync.aligned.m16n8k16.row.col.f32.f16.f16.f32 "
                 "{%0,%1,%2,%3}, {%4,%5,%6,%7}, {%8,%9}, {%0,%1,%2,%3};"
                 : "+f"(d[0]), "+f"(d[1]), "+f"(d[2]), "+f"(d[3])
                 : "r"(a[0]), "r"(a[1]), "r"(a[2]), "r"(a[3]), "r"(b[0]), "r"(b[1]));
}

// write fp16 hi/lo split of a float4 into A-split layout
__device__ __forceinline__ void store_split4(__half* base, int c, float4 r) {
    __half h0 = __float2half_rn(r.x), h1 = __float2half_rn(r.y);
    __half h2 = __float2half_rn(r.z), h3 = __float2half_rn(r.w);
    __half l0 = __float2half_rn(r.x - __half2float(h0));
    __half l1 = __float2half_rn(r.y - __half2float(h1));
    __half l2 = __float2half_rn(r.z - __half2float(h2));
    __half l3 = __float2half_rn(r.w - __half2float(h3));
    *(__half2*)(base + c)           = __halves2half2(h0, h1);
    *(__half2*)(base + c + 2)       = __halves2half2(h2, h3);
    *(__half2*)(base + 768 + c)     = __halves2half2(l0, l1);
    *(__half2*)(base + 768 + c + 2) = __halves2half2(l2, l3);
}

// ---------------- ||c||^2 per codeword (fp64 + fp32 copy) --------------------------
__global__ void norms_kernel(const float* __restrict__ cb) {
    int w = (blockIdx.x * blockDim.x + threadIdx.x) >> 5;
    int lane = threadIdx.x & 31;
    if (w >= NQ * NV) return;
    const float* c = cb + (size_t)w * DIM;
    double s = 0.0;
    #pragma unroll 4
    for (int d = lane; d < DIM; d += 32) {
        double v = (double)__ldg(c + d);
        s = fma(v, v, s);
    }
    #pragma unroll
    for (int o = 16; o; o >>= 1) s += __shfl_xor_sync(0xffffffffu, s, o);
    if (lane == 0) { g_norms64[w] = s; g_norms[w] = (float)s; }
}

// ---------------- residual = x (+ split), quantized = 0, flags = 0 ------------------
__global__ void init_kernel(const float* __restrict__ x) {
    size_t i = (size_t)blockIdx.x * blockDim.x + threadIdx.x;
    if (i < NQ) g_nflag[i] = 0;
    if (i >= (size_t)NROWS * DIM / 4) return;
    float4 v = ((const float4*)x)[i];
    ((float4*)g_residual)[i] = v;
    ((float4*)g_quantized)[i] = make_float4(0.f, 0.f, 0.f, 0.f);
    int row = (int)(i / (DIM / 4));
    int c = (int)(i - (size_t)row * (DIM / 4)) * 4;
    store_split4(g_Asplit + (size_t)row * ACOLS, c, v);
}

// ---------------- split codebooks (once): B' = [c0 | c1 | c0] fp16 ------------------
__global__ void splitB_kernel(const float* __restrict__ cb) {
    int i = blockIdx.x * blockDim.x + threadIdx.x;
    if (i >= NQ * NV * (DIM / 4)) return;
    int qv = i / (DIM / 4);
    int d4 = (i - qv * (DIM / 4)) * 4;
    float4 v = *(const float4*)(cb + (size_t)qv * DIM + d4);
    __half h0 = __float2half_rn(v.x), h1 = __float2half_rn(v.y);
    __half h2 = __float2half_rn(v.z), h3 = __float2half_rn(v.w);
    __half l0 = __float2half_rn(v.x - __half2float(h0));
    __half l1 = __float2half_rn(v.y - __half2float(h1));
    __half l2 = __float2half_rn(v.z - __half2float(h2));
    __half l3 = __float2half_rn(v.w - __half2float(h3));
    __half* base = g_Bsplit + (size_t)qv * BCOLS;
    __half2 hA = __halves2half2(h0, h1), hB = __halves2half2(h2, h3);
    *(__half2*)(base + d4)            = hA;
    *(__half2*)(base + d4 + 2)        = hB;
    *(__half2*)(base + 768 + d4)      = __halves2half2(l0, l1);
    *(__half2*)(base + 768 + d4 + 2)  = __halves2half2(l2, l3);
    *(__half2*)(base + 1536 + d4)     = hA;
    *(__half2*)(base + 1536 + d4 + 2) = hB;
}

// ---------------- mma.sync score GEMM + per-row/segment top-2 ----------------------
// grid = MT2*NT2 (nt fastest), 256 threads = 8 warps (2m x 4n), warp tile 64x32
// 3-buffer cp.async ring, BK=64, one __syncthreads per stage.
__global__ void __launch_bounds__(256, 2)
score_gemm_kernel(int q) {
    extern __shared__ char dyn[];
    __shared__ float snorm[GBN];
    const uint32_t sbase = smem_u32(dyn);

    const int tid = threadIdx.x;
    const int wid = tid >> 5;
    const int lane = tid & 31;
    const int nt = blockIdx.x & (NT2 - 1);
    const int mt = blockIdx.x >> 5;
    const int block_m = mt * GBM;
    const int ncol0 = nt * GBN;
    const int warp_m = (wid >> 2) * 64;
    const int warp_n = (wid & 3) * 32;

    if (tid < GBN) snorm[tid] = g_norms[q * NV + ncol0 + tid];

    const char* Abase = (const char*)g_Asplit + (size_t)block_m * ACOLS * 2;
    const char* Bbase = (const char*)(g_Bsplit + (size_t)q * NV * BCOLS)
                        + (size_t)ncol0 * BCOLS * 2;

    auto issue = [&](int s) {
        const int b = s % NBUF;
        const int k0 = s * BK;
        const int acol = (s < 12) ? k0 : k0 - 768;   // r0, r0, r1 segments
        const uint32_t dA = sbase + b * (2 * BUFSZ);
        const uint32_t dB = dA + BUFSZ;
        const char* Ab = Abase + (size_t)acol * 2;
        const char* Bb = Bbase + (size_t)k0 * 2;
        #pragma unroll
        for (int i = 0; i < 4; i++) {                 // 1024 16B chunks for A
            int ch = tid + i * 256;
            int r = ch >> 3, c16 = (ch & 7) * 16;
            cp16(dA + r * SROWB + c16, Ab + (size_t)r * (ACOLS * 2) + c16);
        }
        #pragma unroll
        for (int i = 0; i < 4; i++) {                 // 1024 16B chunks for B
            int ch = tid + i * 256;
            int r = ch >> 3, c16 = (ch & 7) * 16;
            cp16(dB + r * SROWB + c16, Bb + (size_t)r * (BCOLS * 2) + c16);
        }
        cp_commit();
    };

    float acc[4][4][4];
    #pragma unroll
    for (int im = 0; im < 4; im++)
        #pragma unroll
        for (int in = 0; in < 4; in++)
            #pragma unroll
            for (int e = 0; e < 4; e++) acc[im][in][e] = 0.f;

    issue(0);
    issue(1);

    const int arow = lane & 15;
    const int acolh = (lane >> 4) * 8;
    const int brow = lane & 7;
    const int bcolh = ((lane >> 3) & 1) * 8;

    #pragma unroll 1
    for (int s = 0; s < NSTG; ++s) {
        if (s < NSTG - 1) cp_wait<1>(); else cp_wait<0>();
        __syncthreads();
        if (s + 2 < NSTG) issue(s + 2);   // writes buf (s+2)%3 (= stage s-1's, done)

        const uint32_t aB = sbase + (s % NBUF) * (2 * BUFSZ);
        const uint32_t bB = aB + BUFSZ;
        #pragma unroll
        for (int kk = 0; kk < 4; kk++) {
            const int k0 = kk * 16;
            uint32_t afr[4][4];
            #pragma unroll
            for (int im = 0; im < 4; im++) {
                uint32_t addr = aB + (warp_m + im * 16 + arow) * SROWB + (k0 + acolh) * 2;
                ldm_x4(afr[im], addr);
            }
            #pragma unroll
            for (int in = 0; in < 4; in++) {
                uint32_t bfr[2];
                uint32_t addr = bB + (warp_n + in * 8 + brow) * SROWB + (k0 + bcolh) * 2;
                ldm_x2(bfr, addr);
                #pragma unroll
                for (int im = 0; im < 4; im++) mma16816(acc[im][in], afr[im], bfr);
            }
        }
    }

    // epilogue: per-row top-2 over this warp's 32 cols; quad-merge; write partials.
    const int seg = nt * 4 + (wid & 3);
    #pragma unroll
    for (int im = 0; im < 4; im++) {
        float t1a = -1e30f, t2a = -1e30f, t1b = -1e30f, t2b = -1e30f;
        int i1a = 0, i1b = 0;
        #pragma unroll
        for (int in = 0; in < 4; in++) {
            int c = warp_n + in * 8 + (lane & 3) * 2;
            float n0 = snorm[c], n1 = snorm[c + 1];
            float sa0 = fmaf(2.f, acc[im][in][0], -n0);
            float sa1 = fmaf(2.f, acc[im][in][1], -n1);
            float sb0 = fmaf(2.f, acc[im][in][2], -n0);
            float sb1 = fmaf(2.f, acc[im][in][3], -n1);
            int gc = ncol0 + c;
            if (sa0 > t1a) { t2a = t1a; t1a = sa0; i1a = gc; } else if (sa0 > t2a) t2a = sa0;
            if (sa1 > t1a) { t2a = t1a; t1a = sa1; i1a = gc + 1; } else if (sa1 > t2a) t2a = sa1;
            if (sb0 > t1b) { t2b = t1b; t1b = sb0; i1b = gc; } else if (sb0 > t2b) t2b = sb0;
            if (sb1 > t1b) { t2b = t1b; t1b = sb1; i1b = gc + 1; } else if (sb1 > t2b) t2b = sb1;
        }
        #pragma unroll
        for (int o = 1; o < 4; o <<= 1) {
            float u1 = __shfl_xor_sync(0xffffffffu, t1a, o);
            float u2 = __shfl_xor_sync(0xffffffffu, t2a, o);
            int   ui = __shfl_xor_sync(0xffffffffu, i1a, o);
            if (u1 > t1a || (u1 == t1a && ui < i1a)) { t2a = fmaxf(t1a, u2); t1a = u1; i1a = ui; }
            else t2a = fmaxf(t2a, u1);
            float v1 = __shfl_xor_sync(0xffffffffu, t1b, o);
            float v2 = __shfl_xor_sync(0xffffffffu, t2b, o);
            int   vi = __shfl_xor_sync(0xffffffffu, i1b, o);
            if (v1 > t1b || (v1 == t1b && vi < i1b)) { t2b = fmaxf(t1b, v2); t1b = v1; i1b = vi; }
            else t2b = fmaxf(t2b, v1);
        }
        if ((lane & 3) == 0) {
            int rA = block_m + warp_m + im * 16 + (lane >> 2);
            g_part[(size_t)rA * NSEG + seg] = make_float4(t1a, t2a, __int_as_float(i1a), 0.f);
            g_part[(size_t)(rA + 8) * NSEG + seg] = make_float4(t1b, t2b, __int_as_float(i1b), 0.f);
        }
    }
}

// ---------------- merge partials -> global top-2, index, flag list ------------------
__global__ void merge_kernel(int q) {
    int row = blockIdx.x * blockDim.x + threadIdx.x;
    if (row >= NROWS) return;
    float b1 = -1e30f, b2 = -1e30f;
    int bi = 0;
    const float4* p = &g_part[(size_t)row * NSEG];
    #pragma unroll 8
    for (int s = 0; s < NSEG; s++) {
        float4 v = p[s];   // segments ascending in col index: first-max-wins
        if (v.x > b1) { b2 = fmaxf(b1, v.y); b1 = v.x; bi = __float_as_int(v.z); }
        else          { b2 = fmaxf(b2, v.x); }
    }
    g_indices[row * NQ + q] = bi;
    if (b1 - b2 < DELTA) {
        int pos = atomicAdd(&g_nflag[q], 1);
        g_flaglist[q * NROWS + pos] = row;
    }
}

// ---------------- fp64 exhaustive refine for near-tie rows --------------------------
__global__ void __launch_bounds__(256, 1)
refine_kernel(const float* __restrict__ cb, int q) {
    __shared__ float  rsm[DIM];
    __shared__ double sred[256];
    __shared__ int    ired[256];

    const int tid = threadIdx.x;
    const int nf = g_nflag[q];

    for (int jj = blockIdx.x; jj < nf; jj += gridDim.x) {
        const int row = g_flaglist[q * NROWS + jj];
        for (int d = tid; d < DIM; d += 256) rsm[d] = g_residual[(size_t)row * DIM + d];
        __syncthreads();

        double best = -1e300;
        int bidx = 0;
        for (int v = tid; v < NV; v += 256) {
            const float4* cv = (const float4*)(cb + (size_t)v * DIM);
            double a0 = 0, a1 = 0, a2 = 0, a3 = 0, a4 = 0, a5 = 0, a6 = 0, a7 = 0;
            #pragma unroll 4
            for (int t = 0; t < DIM / 4; t += 2) {
                float4 c0 = __ldg(cv + t);
                float4 c1 = __ldg(cv + t + 1);
                const float4 r0 = *(const float4*)&rsm[4 * t];
                const float4 r1 = *(const float4*)&rsm[4 * t + 4];
                a0 = fma((double)r0.x, (double)c0.x, a0);
                a1 = fma((double)r0.y, (double)c0.y, a1);
                a2 = fma((double)r0.z, (double)c0.z, a2);
                a3 = fma((double)r0.w, (double)c0.w, a3);
                a4 = fma((double)r1.x, (double)c1.x, a4);
                a5 = fma((double)r1.y, (double)c1.y, a5);
                a6 = fma((double)r1.z, (double)c1.z, a6);
                a7 = fma((double)r1.w, (double)c1.w, a7);
            }
            double dot = ((a0 + a1) + (a2 + a3)) + ((a4 + a5) + (a6 + a7));
            double s = 2.0 * dot - g_norms64[q * NV + v];
            if (s > best) { best = s; bidx = v; }
        }
        sred[tid] = best; ired[tid] = bidx;
        __syncthreads();
        for (int o = 128; o; o >>= 1) {
            if (tid < o) {
                double so = sred[tid + o]; int vo = ired[tid + o];
                if (so > sred[tid] || (so == sred[tid] && vo < ired[tid])) {
                    sred[tid] = so; ired[tid] = vo;
                }
            }
            __syncthreads();
        }
        if (tid == 0) g_indices[row * NQ + q] = ired[0];
        __syncthreads();
    }
}

// ---------------- gather + residual/quantized update (+ fp16 split of residual) -----
__global__ void update_kernel(const float* __restrict__ cb, int q) {
    int gid = blockIdx.x * blockDim.x + threadIdx.x;
    const int PR = DIM / 4;
    int row = gid / PR;
    if (row >= NROWS) return;
    int c = (gid - row * PR) << 2;
    int idx = __ldg(&g_indices[row * NQ + q]);
    const float4 cw = *(const float4*)(cb + (size_t)idx * DIM + c);
    size_t off = (size_t)row * DIM + c;
    float4 r = *(float4*)(g_residual + off);
    float4 z = *(float4*)(g_quantized + off);
    r.x -= cw.x; r.y -= cw.y; r.z -= cw.z; r.w -= cw.w;
    z.x += cw.x; z.y += cw.y; z.z += cw.z; z.w += cw.w;
    *(float4*)(g_residual + off) = r;
    *(float4*)(g_quantized + off) = z;
    store_split4(g_Asplit + (size_t)row * ACOLS, c, r);  // next level's A
}

// ---------------- out = x + (quantized - x) -----------------------------------------
__global__ void finalize_kernel(const float* __restrict__ x, float* __restrict__ out) {
    size_t i = (size_t)blockIdx.x * blockDim.x + threadIdx.x;
    if (i >= (size_t)NROWS * DIM / 4) return;
    float4 xv = ((const float4*)x)[i];
    float4 qv = ((const float4*)g_quantized)[i];
    float4 o;
    o.x = xv.x + (qv.x - xv.x);
    o.y = xv.y + (qv.y - xv.y);
    o.z = xv.z + (qv.z - xv.z);
    o.w = xv.w + (qv.w - xv.w);
    ((float4*)out)[i] = o;
}

__global__ void idxout_kernel(float* __restrict__ out) {
    int i = blockIdx.x * blockDim.x + threadIdx.x;
    if (i < NROWS * NQ) out[i] = (float)g_indices[i];
}

extern "C" void kernel_launch(void* const* d_in, const int* in_sizes, int n_in,
                              void* d_out, int out_size) {
    const float* x  = (const float*)d_in[0];
    const float* cb = (const float*)d_in[1];
    float* out = (float*)d_out;

    cudaFuncSetAttribute(score_gemm_kernel,
                         cudaFuncAttributeMaxDynamicSharedMemorySize, SMEM_DYN);

    norms_kernel<<<(NQ * NV) / 8, 256>>>(cb);
    init_kernel<<<(NROWS * DIM / 4 + 255) / 256, 256>>>(x);
    splitB_kernel<<<(NQ * NV * (DIM / 4) + 255) / 256, 256>>>(cb);

    for (int q = 0; q < NQ; q++) {
        const float* cbq = cb + (size_t)q * NV * DIM;
        score_gemm_kernel<<<MT2 * NT2, 256, SMEM_DYN>>>(q);
        merge_kernel<<<(NROWS + 255) / 256, 256>>>(q);
        refine_kernel<<<148, 256>>>(cbq, q);
        update_kernel<<<(NROWS * (DIM / 4) + 255) / 256, 256>>>(cbq, q);
    }

    finalize_kernel<<<(NROWS * DIM / 4 + 255) / 256, 256>>>(x, out);

    if (out_size >= NROWS * DIM + NROWS * NQ) {
        idxout_kernel<<<(NROWS * NQ + 255) / 256, 256>>>(out + (size_t)NROWS * DIM);
    }
}